// round 8
// baseline (speedup 1.0000x reference)
#include <cuda_runtime.h>
#include <cuda_fp16.h>
#include <cstdint>

#define D_MODEL 1024
#define BB 2
#define SS 2048
#define NTOK (BB*SS)
#define V1N 200
#define V2N 160
#define NL 8
#define TC 32
#define NC (SS/TC)     /* 64 */
#define NBLK (BB*NC)   /* 128 */
#define EPS 1e-6f
#define PITCH 40

// ---------------- scratch -------------------------------------------------
__device__ float g_hfin[2][NBLK * D_MODEL];    // chunk-local scan results (ping-pong)
__device__ unsigned g_barcnt[NL];              // monotone grid-barrier counters
__device__ uint32_t g_c1h[13 * 256];           // c1 fp16 frags: [mt][lane][ks][j]
__device__ uint32_t g_c2h[10 * 256];           // c2 fp16 frags: [mt][lane][ks][j]

// ---------------- helpers -------------------------------------------------
__device__ __forceinline__ float warp_sum(float v){
#pragma unroll
    for (int o = 16; o; o >>= 1) v += __shfl_xor_sync(0xffffffffu, v, o);
    return v;
}
__device__ __forceinline__ float sigmoidf_(float x){ return 1.f / (1.f + expf(-x)); }
__device__ __forceinline__ float geluf_(float x){
    float x3 = x * x * x;
    return 0.5f * x * (1.f + tanhf(0.7978845608028654f * (x + 0.044715f * x3)));
}
__device__ __forceinline__ void mma16816(float& d0, float& d1, float& d2, float& d3,
                                         uint32_t a0, uint32_t a1, uint32_t a2, uint32_t a3,
                                         uint32_t b0, uint32_t b1){
    asm volatile(
        "mma.sync.aligned.m16n8k16.row.col.f32.f16.f16.f32 "
        "{%0,%1,%2,%3},{%4,%5,%6,%7},{%8,%9},{%0,%1,%2,%3};\n"
        : "+f"(d0), "+f"(d1), "+f"(d2), "+f"(d3)
        : "r"(a0), "r"(a1), "r"(a2), "r"(a3), "r"(b0), "r"(b1));
}

__device__ __forceinline__ void grid_bar(int i){
    __syncthreads();
    if (threadIdx.x == 0){
        __threadfence();
        unsigned my = atomicAdd(&g_barcnt[i], 1u);
        unsigned target = (my | (unsigned)(NBLK - 1)) + 1u;
        while (*(volatile unsigned*)&g_barcnt[i] < target) {}
    }
    __syncthreads();
}

// =========================================================================
// single persistent kernel: embed + 8 fused layers + logits.
// block = one chunk (32 tokens x 1024 channels), grid = 128 (one wave).
// =========================================================================
__global__ __launch_bounds__(1024, 1) void k_model(
    const int* __restrict__ ids, const float* __restrict__ c1,
    const float* __restrict__ c2, const float* __restrict__ lam,
    const float* __restrict__ uu, const float* __restrict__ vv,
    const float* __restrict__ w1, const float* __restrict__ w2,
    const float* __restrict__ n1w, const float* __restrict__ n2w,
    const float* __restrict__ fw, float* __restrict__ out)
{
    extern __shared__ float sx[];              // TC * D_MODEL = 128 KB
    __shared__ float s_n2w[D_MODEL], s_w1x[D_MODEL], s_w1y[D_MODEL];
    __shared__ float s_w2a[D_MODEL], s_w2b[D_MODEL];
    __shared__ float s_fw[D_MODEL];
    __shared__ float s_ir[TC];
    __shared__ half  s_xh[32 * PITCH];         // fp16 token (B-frag layout)
    __shared__ half  s_Yt[2][160 * PITCH];     // stage-1 double buffer

    int b  = blockIdx.x >> 6;
    int ch = blockIdx.x & (NC - 1);
    int c  = threadIdx.x;
    int t  = c >> 5, lane = c & 31;
    int tok0 = b * SS + ch * TC;

    s_fw[c] = fw[c];                            // stage final-norm weights early

    // ---- embed (warp = token) into smem ----
    {
        int id = ids[tok0 + t];
        const float* r1 = c1 + (id / V2N) * 32;
        const float* r2 = c2 + (id % V2N) * 32;
        float* xr = sx + t * D_MODEL;
        float ss = 0.f;
#pragma unroll
        for (int k = 0; k < 8; k++){
            int e = k * 128 + lane * 4;
            float a = r1[e >> 5];
            float4 bq = *(const float4*)(r2 + (e & 31));
            float4 v4; v4.x = a*bq.x; v4.y = a*bq.y; v4.z = a*bq.z; v4.w = a*bq.w;
            *(float4*)(xr + e) = v4;
            ss += v4.x*v4.x + v4.y*v4.y + v4.z*v4.z + v4.w*v4.w;
        }
        ss = warp_sum(ss);
        if (lane == 0) s_ir[t] = rsqrtf(ss * (1.f/1024.f) + EPS);
    }
    __syncthreads();

    // ---- phase A for layer 0 ----
    {
        float a0  = sigmoidf_(lam[c]);
        float vn0 = vv[c] * n1w[c];
        float h = 0.f;
#pragma unroll
        for (int tt = 0; tt < TC; tt++)
            h = fmaf(a0, h, (vn0 * s_ir[tt]) * sx[tt * D_MODEL + c]);
        g_hfin[0][blockIdx.x * D_MODEL + c] = h;
    }

    // ---- block 0: pack c1/c2 into fp16 MMA A-fragment tables ----
    if (blockIdx.x == 0){
        const int T1 = 13 * 256, T2 = 10 * 256;
        for (int idx = c; idx < T1 + T2; idx += 1024){
            bool is1 = idx < T1;
            int rem  = is1 ? idx : idx - T1;
            int j = rem & 3, ks = (rem >> 2) & 1, ln = (rem >> 3) & 31, mt = rem >> 8;
            int gg = ln >> 2, tg2 = ln & 3;
            int row = mt * 16 + gg + (j & 1) * 8;
            int col = ks * 16 + 2 * tg2 + ((j >> 1) & 1) * 8;
            if (is1){
                uint32_t val = 0;
                if (row < V1N){
                    half2 h = __floats2half2_rn(c1[row * 32 + col], c1[row * 32 + col + 1]);
                    val = *(uint32_t*)&h;
                }
                g_c1h[rem] = val;
            } else {
                half2 h = __floats2half2_rn(c2[row * 32 + col], c2[row * 32 + col + 1]);
                g_c2h[rem] = *(uint32_t*)&h;
            }
        }
    }

    // =================== 8 fused layers ===================
    for (int l = 0; l < NL; l++){
        grid_bar(l);

        float w_n2 = n2w[l * D_MODEL + c];
        float2 w1p = ((const float2*)(w1 + (size_t)l * D_MODEL * 2))[c];
        float w2av = w2[(size_t)l * 2 * D_MODEL + c];
        float w2bv = w2[(size_t)l * 2 * D_MODEL + D_MODEL + c];

        int off = l * D_MODEL + c;
        float a  = sigmoidf_(lam[off]);
        float vn = vv[off] * n1w[off];
        float un = uu[off];
        float aT = a * a; aT *= aT; aT *= aT; aT *= aT; aT *= aT;   // a^32

        const float* hf = g_hfin[l & 1] + (size_t)b * NC * D_MODEL + c;
        float carry = 0.f;
#pragma unroll 16
        for (int k = 0; k < ch; k++)
            carry = fmaf(aT, carry, __ldcg(hf + (size_t)k * D_MODEL));

        s_n2w[c] = w_n2; s_w1x[c] = w1p.x; s_w1y[c] = w1p.y;
        s_w2a[c] = w2av; s_w2b[c] = w2bv;

        float h = carry;
#pragma unroll
        for (int tt = 0; tt < TC; tt++){
            float xv = sx[tt * D_MODEL + c];
            h = fmaf(a, h, (vn * s_ir[tt]) * xv);
            sx[tt * D_MODEL + c] = fmaf(un, h, xv);
        }
        __syncthreads();

        float* xr = sx + t * D_MODEL;
        float xv[32];
        float ss = 0.f;
#pragma unroll
        for (int k = 0; k < 8; k++){
            float4 q = *(const float4*)(xr + k * 128 + lane * 4);
            xv[4*k]=q.x; xv[4*k+1]=q.y; xv[4*k+2]=q.z; xv[4*k+3]=q.w;
            ss += q.x*q.x + q.y*q.y + q.z*q.z + q.w*q.w;
        }
        ss = warp_sum(ss);
        float invr = rsqrtf(ss * (1.f/1024.f) + EPS);

        float d0 = 0.f, d1 = 0.f;
#pragma unroll
        for (int k = 0; k < 8; k++){
            int e = k * 128 + lane * 4;
            float4 nw = *(const float4*)(s_n2w + e);
            float4 wx = *(const float4*)(s_w1x + e);
            float4 wy = *(const float4*)(s_w1y + e);
#pragma unroll
            for (int r = 0; r < 4; r++){
                float hh = xv[4*k+r] * invr * ((const float*)&nw)[r];
                d0 = fmaf(hh, ((const float*)&wx)[r], d0);
                d1 = fmaf(hh, ((const float*)&wy)[r], d1);
            }
        }
        d0 = warp_sum(d0);
        d1 = warp_sum(d1);
        float g0 = geluf_(d0), g1 = geluf_(d1);

        float ss2 = 0.f;
#pragma unroll
        for (int k = 0; k < 8; k++){
            int e = k * 128 + lane * 4;
            float4 wa = *(const float4*)(s_w2a + e);
            float4 wb = *(const float4*)(s_w2b + e);
            float4 o;
            o.x = xv[4*k+0] + g0*wa.x + g1*wb.x;
            o.y = xv[4*k+1] + g0*wa.y + g1*wb.y;
            o.z = xv[4*k+2] + g0*wa.z + g1*wb.z;
            o.w = xv[4*k+3] + g0*wa.w + g1*wb.w;
            *(float4*)(xr + e) = o;
            ss2 += o.x*o.x + o.y*o.y + o.z*o.z + o.w*o.w;
        }
        ss2 = warp_sum(ss2);
        if (lane == 0) s_ir[t] = rsqrtf(ss2 * (1.f/1024.f) + EPS);
        __syncthreads();

        if (l < NL - 1){
            int off2 = (l + 1) * D_MODEL + c;
            float a2  = sigmoidf_(lam[off2]);
            float vn2 = vv[off2] * n1w[off2];
            float h2 = 0.f;
#pragma unroll
            for (int tt = 0; tt < TC; tt++)
                h2 = fmaf(a2, h2, (vn2 * s_ir[tt]) * sx[tt * D_MODEL + c]);
            g_hfin[(l + 1) & 1][blockIdx.x * D_MODEL + c] = h2;
        }
    }

    // =================== logits tail (this block's 32 tokens) ===============
    // warps 0-3 : convert token i -> s_xh (fp16), named bar, stage-1 -> Yt[i&1]
    // warps 4-31: stage-2 for token i-1 from Yt[(i-1)&1], A-frags in regs
    int w = t, g = lane >> 2, tg = lane & 3;
    const uint4* c1f = (const uint4*)g_c1h;
    const uint4* c2f = (const uint4*)g_c2h;

    int start = 0, end = 0, mt0 = 0, nmt = 0;
    uint4 qa[2][2];
    if (w >= 4){
        int s2w = w - 4;                       // 0..27
        start = s2w * 260 / 28;
        end   = (s2w + 1) * 260 / 28;
        mt0   = start / 20;
        nmt   = (end - 1) / 20 - mt0 + 1;      // <= 2
#pragma unroll
        for (int m = 0; m < 2; m++)
            if (m < nmt){
                qa[m][0] = __ldg(&c1f[((mt0 + m) * 32 + lane) * 2 + 0]);
                qa[m][1] = __ldg(&c1f[((mt0 + m) * 32 + lane) * 2 + 1]);
            }
    }

    for (int i = 0; i <= TC; i++){
        if (w < 4 && i < TC){
            // convert token i (8 elems/thread among 128 threads)
            float invr = s_ir[i];
            int thr = w * 32 + lane;
            int e0 = thr * 8;
            const float* xp = sx + i * D_MODEL + e0;
            const float* fp = s_fw + e0;
            half2 h0 = __floats2half2_rn(xp[0]*invr*fp[0], xp[1]*invr*fp[1]);
            half2 h1 = __floats2half2_rn(xp[2]*invr*fp[2], xp[3]*invr*fp[3]);
            half2 h2 = __floats2half2_rn(xp[4]*invr*fp[4], xp[5]*invr*fp[5]);
            half2 h3 = __floats2half2_rn(xp[6]*invr*fp[6], xp[7]*invr*fp[7]);
            half* dst = s_xh + (e0 >> 5) * PITCH + (e0 & 31);
            *(uint2*)(dst)     = make_uint2(*(uint32_t*)&h0, *(uint32_t*)&h1);
            *(uint2*)(dst + 4) = make_uint2(*(uint32_t*)&h2, *(uint32_t*)&h3);
            asm volatile("bar.sync 1, 128;" ::: "memory");

            // stage 1: 10 tiles per warp (ids w*10 .. w*10+9)
            half* yt = s_Yt[i & 1];
            for (int id = w * 10; id < w * 10 + 10; id++){
                int mt = id >> 2, nt = id & 3;
                uint4 qb0 = __ldg(&c2f[(mt * 32 + lane) * 2 + 0]);
                uint4 qb1 = __ldg(&c2f[(mt * 32 + lane) * 2 + 1]);
                float a0c = 0.f, a1c = 0.f, a2c = 0.f, a3c = 0.f;
                int ac = 2 * tg;
                const half* xb = s_xh + (nt*8 + g) * PITCH;
                uint32_t B0 = *(const uint32_t*)(xb + ac);
                uint32_t B1 = *(const uint32_t*)(xb + ac + 8);
                mma16816(a0c, a1c, a2c, a3c, qb0.x, qb0.y, qb0.z, qb0.w, B0, B1);
                B0 = *(const uint32_t*)(xb + ac + 16);
                B1 = *(const uint32_t*)(xb + ac + 24);
                mma16816(a0c, a1c, a2c, a3c, qb1.x, qb1.y, qb1.z, qb1.w, B0, B1);
                int col = nt * 8 + 2 * tg;
                *(half2*)(yt + (mt*16 + g    ) * PITCH + col) = __floats2half2_rn(a0c, a1c);
                *(half2*)(yt + (mt*16 + g + 8) * PITCH + col) = __floats2half2_rn(a2c, a3c);
            }
        }
        if (w >= 4 && i > 0){
            const half* yt = s_Yt[(i - 1) & 1];
            float* op = out + (size_t)(tok0 + i - 1) * (V1N * V2N);
            int id = start;
#pragma unroll
            for (int m = 0; m < 2; m++){
                if (m < nmt){
                    int mt = mt0 + m;
                    int ntEnd = min(end, (mt + 1) * 20);
                    for (; id < ntEnd; id++){
                        int nt = id - mt * 20;
                        float a0c = 0.f, a1c = 0.f, a2c = 0.f, a3c = 0.f;
                        int ac = 2 * tg;
                        const half* yb = yt + (nt*8 + g) * PITCH;
                        uint32_t B0 = *(const uint32_t*)(yb + ac);
                        uint32_t B1 = *(const uint32_t*)(yb + ac + 8);
                        mma16816(a0c, a1c, a2c, a3c, qa[m][0].x, qa[m][0].y,
                                 qa[m][0].z, qa[m][0].w, B0, B1);
                        B0 = *(const uint32_t*)(yb + ac + 16);
                        B1 = *(const uint32_t*)(yb + ac + 24);
                        mma16816(a0c, a1c, a2c, a3c, qa[m][1].x, qa[m][1].y,
                                 qa[m][1].z, qa[m][1].w, B0, B1);
                        int r0 = mt * 16 + g, col = nt * 8 + 2 * tg;
                        __stcs((float2*)(op + r0 * V2N + col), make_float2(a0c, a1c));
                        if (r0 + 8 < V1N)
                            __stcs((float2*)(op + (r0 + 8) * V2N + col), make_float2(a2c, a3c));
                    }
                }
            }
        }
        __syncthreads();
    }
}

// ---------------- launch --------------------------------------------------
extern "C" void kernel_launch(void* const* d_in, const int* in_sizes, int n_in,
                              void* d_out, int out_size){
    const int*   ids = (const int*)  d_in[0];
    const float* c1  = (const float*)d_in[1];
    const float* c2  = (const float*)d_in[2];
    const float* lam = (const float*)d_in[3];
    const float* u   = (const float*)d_in[4];
    const float* v   = (const float*)d_in[5];
    const float* w1  = (const float*)d_in[6];
    const float* w2  = (const float*)d_in[7];
    const float* n1w = (const float*)d_in[8];
    const float* n2w = (const float*)d_in[9];
    const float* fw  = (const float*)d_in[10];
    float* out = (float*)d_out;

    const int smem = TC * D_MODEL * sizeof(float);   // 128 KB dynamic
    static bool attr_set = false;
    if (!attr_set){
        cudaFuncSetAttribute(k_model, cudaFuncAttributeMaxDynamicSharedMemorySize, smem);
        attr_set = true;
    }

    k_model<<<NBLK, 1024, smem>>>(ids, c1, c2, lam, u, v, w1, w2, n1w, n2w, fw, out);
}

// round 9
// speedup vs baseline: 1.1254x; 1.1254x over previous
#include <cuda_runtime.h>
#include <cuda_fp16.h>
#include <cstdint>

#define D_MODEL 1024
#define BB 2
#define SS 2048
#define NTOK (BB*SS)
#define V1N 200
#define V2N 160
#define NL 8
#define TC 32
#define NC (SS/TC)     /* 64 */
#define NBLK (BB*NC)   /* 128 */
#define EPS 1e-6f
#define PITCH 40
#define TPB 4

// ---------------- scratch -------------------------------------------------
__device__ half  g_xh[NTOK * D_MODEL];         // final normalized token (fp16)
__device__ float g_hfin[NL][NBLK * D_MODEL];   // per-layer chunk-local scan results
__device__ unsigned g_flag[NL][NBLK];          // monotone per-block ready flags
__device__ uint32_t g_c1h[13 * 256];           // c1 fp16 frags: [mt][lane][ks][j]
__device__ uint32_t g_c2h[10 * 256];           // c2 fp16 frags: [mt][lane][ks][j]

// ---------------- helpers -------------------------------------------------
__device__ __forceinline__ float warp_sum(float v){
#pragma unroll
    for (int o = 16; o; o >>= 1) v += __shfl_xor_sync(0xffffffffu, v, o);
    return v;
}
__device__ __forceinline__ float sigmoidf_(float x){ return 1.f / (1.f + expf(-x)); }
__device__ __forceinline__ float geluf_(float x){
    float x3 = x * x * x;
    return 0.5f * x * (1.f + tanhf(0.7978845608028654f * (x + 0.044715f * x3)));
}
__device__ __forceinline__ unsigned ld_acq(const unsigned* p){
    unsigned v;
    asm volatile("ld.acquire.gpu.global.u32 %0, [%1];" : "=r"(v) : "l"(p));
    return v;
}
__device__ __forceinline__ void mma16816(float& d0, float& d1, float& d2, float& d3,
                                         uint32_t a0, uint32_t a1, uint32_t a2, uint32_t a3,
                                         uint32_t b0, uint32_t b1){
    asm volatile(
        "mma.sync.aligned.m16n8k16.row.col.f32.f16.f16.f32 "
        "{%0,%1,%2,%3},{%4,%5,%6,%7},{%8,%9},{%0,%1,%2,%3};\n"
        : "+f"(d0), "+f"(d1), "+f"(d2), "+f"(d3)
        : "r"(a0), "r"(a1), "r"(a2), "r"(a3), "r"(b0), "r"(b1));
}

// =========================================================================
// model kernel: embed + 8 fused layers; x stays in smem; wavefront flags.
// block = one chunk (32 tokens x 1024 channels), grid = 128 (one wave).
// =========================================================================
__global__ __launch_bounds__(1024, 1) void k_model(
    const int* __restrict__ ids, const float* __restrict__ c1,
    const float* __restrict__ c2, const float* __restrict__ lam,
    const float* __restrict__ uu, const float* __restrict__ vv,
    const float* __restrict__ w1, const float* __restrict__ w2,
    const float* __restrict__ n1w, const float* __restrict__ n2w,
    const float* __restrict__ fw)
{
    extern __shared__ float sx[];              // TC * D_MODEL = 128 KB
    __shared__ float s_n2w[D_MODEL], s_w1x[D_MODEL], s_w1y[D_MODEL];
    __shared__ float s_w2a[D_MODEL], s_w2b[D_MODEL];
    __shared__ float s_ir[TC];
    __shared__ unsigned s_base;

    int b  = blockIdx.x >> 6;
    int ch = blockIdx.x & (NC - 1);
    int c  = threadIdx.x;
    int t  = c >> 5, lane = c & 31;
    int tok0 = b * SS + ch * TC;

    if (c == 0) s_base = g_flag[0][blockIdx.x];   // epoch baseline (replay-safe)

    // ---- embed (warp = token) into smem ----
    {
        int id = ids[tok0 + t];
        const float* r1 = c1 + (id / V2N) * 32;
        const float* r2 = c2 + (id % V2N) * 32;
        float* xr = sx + t * D_MODEL;
        float ss = 0.f;
#pragma unroll
        for (int k = 0; k < 8; k++){
            int e = k * 128 + lane * 4;
            float a = r1[e >> 5];
            float4 bq = *(const float4*)(r2 + (e & 31));
            float4 v4; v4.x = a*bq.x; v4.y = a*bq.y; v4.z = a*bq.z; v4.w = a*bq.w;
            *(float4*)(xr + e) = v4;
            ss += v4.x*v4.x + v4.y*v4.y + v4.z*v4.z + v4.w*v4.w;
        }
        ss = warp_sum(ss);
        if (lane == 0) s_ir[t] = rsqrtf(ss * (1.f/1024.f) + EPS);
    }
    __syncthreads();

    // ---- phase A for layer 0; publish flag[0] ----
    {
        float a0  = sigmoidf_(lam[c]);
        float vn0 = vv[c] * n1w[c];
        float h = 0.f;
#pragma unroll
        for (int tt = 0; tt < TC; tt++)
            h = fmaf(a0, h, (vn0 * s_ir[tt]) * sx[tt * D_MODEL + c]);
        g_hfin[0][blockIdx.x * D_MODEL + c] = h;
    }
    __syncthreads();
    if (c == 0){ __threadfence(); atomicAdd(&g_flag[0][blockIdx.x], 1u); }

    // ---- block 0: pack c1/c2 into fp16 MMA A-fragment tables ----
    if (blockIdx.x == 0){
        const int T1 = 13 * 256, T2 = 10 * 256;
        for (int idx = c; idx < T1 + T2; idx += 1024){
            bool is1 = idx < T1;
            int rem  = is1 ? idx : idx - T1;
            int j = rem & 3, ks = (rem >> 2) & 1, ln = (rem >> 3) & 31, mt = rem >> 8;
            int gg = ln >> 2, tg2 = ln & 3;
            int row = mt * 16 + gg + (j & 1) * 8;
            int col = ks * 16 + 2 * tg2 + ((j >> 1) & 1) * 8;
            if (is1){
                uint32_t val = 0;
                if (row < V1N){
                    half2 h = __floats2half2_rn(c1[row * 32 + col], c1[row * 32 + col + 1]);
                    val = *(uint32_t*)&h;
                }
                g_c1h[rem] = val;
            } else {
                half2 h = __floats2half2_rn(c2[row * 32 + col], c2[row * 32 + col + 1]);
                g_c2h[rem] = *(uint32_t*)&h;
            }
        }
    }

    // =================== 8 fused layers ===================
    for (int l = 0; l < NL; l++){
        // wait only for predecessor chunks (thread k polls chunk k's flag)
        unsigned tgt = s_base + 1;
        if (c < ch){
            const unsigned* fp = &g_flag[l][b * NC + c];
            while (ld_acq(fp) < tgt) {}
        }
        __syncthreads();

        float w_n2 = n2w[l * D_MODEL + c];
        float2 w1p = ((const float2*)(w1 + (size_t)l * D_MODEL * 2))[c];
        float w2av = w2[(size_t)l * 2 * D_MODEL + c];
        float w2bv = w2[(size_t)l * 2 * D_MODEL + D_MODEL + c];

        int off = l * D_MODEL + c;
        float a  = sigmoidf_(lam[off]);
        float vn = vv[off] * n1w[off];
        float un = uu[off];
        float aT = a * a; aT *= aT; aT *= aT; aT *= aT; aT *= aT;   // a^32

        const float* hf = g_hfin[l] + (size_t)b * NC * D_MODEL + c;
        float carry = 0.f;
#pragma unroll 16
        for (int k = 0; k < ch; k++)
            carry = fmaf(aT, carry, __ldcg(hf + (size_t)k * D_MODEL));

        s_n2w[c] = w_n2; s_w1x[c] = w1p.x; s_w1y[c] = w1p.y;
        s_w2a[c] = w2av; s_w2b[c] = w2bv;

        float h = carry;
#pragma unroll
        for (int tt = 0; tt < TC; tt++){
            float xv = sx[tt * D_MODEL + c];
            h = fmaf(a, h, (vn * s_ir[tt]) * xv);
            sx[tt * D_MODEL + c] = fmaf(un, h, xv);
        }
        __syncthreads();

        float* xr = sx + t * D_MODEL;
        float xv[32];
        float ss = 0.f;
#pragma unroll
        for (int k = 0; k < 8; k++){
            float4 q = *(const float4*)(xr + k * 128 + lane * 4);
            xv[4*k]=q.x; xv[4*k+1]=q.y; xv[4*k+2]=q.z; xv[4*k+3]=q.w;
            ss += q.x*q.x + q.y*q.y + q.z*q.z + q.w*q.w;
        }
        ss = warp_sum(ss);
        float invr = rsqrtf(ss * (1.f/1024.f) + EPS);

        float d0 = 0.f, d1 = 0.f;
#pragma unroll
        for (int k = 0; k < 8; k++){
            int e = k * 128 + lane * 4;
            float4 nw = *(const float4*)(s_n2w + e);
            float4 wx = *(const float4*)(s_w1x + e);
            float4 wy = *(const float4*)(s_w1y + e);
#pragma unroll
            for (int r = 0; r < 4; r++){
                float hh = xv[4*k+r] * invr * ((const float*)&nw)[r];
                d0 = fmaf(hh, ((const float*)&wx)[r], d0);
                d1 = fmaf(hh, ((const float*)&wy)[r], d1);
            }
        }
        d0 = warp_sum(d0);
        d1 = warp_sum(d1);
        float g0 = geluf_(d0), g1 = geluf_(d1);

        float ss2 = 0.f;
#pragma unroll
        for (int k = 0; k < 8; k++){
            int e = k * 128 + lane * 4;
            float4 wa = *(const float4*)(s_w2a + e);
            float4 wb = *(const float4*)(s_w2b + e);
            float4 o;
            o.x = xv[4*k+0] + g0*wa.x + g1*wb.x;
            o.y = xv[4*k+1] + g0*wa.y + g1*wb.y;
            o.z = xv[4*k+2] + g0*wa.z + g1*wb.z;
            o.w = xv[4*k+3] + g0*wa.w + g1*wb.w;
            xv[4*k+0]=o.x; xv[4*k+1]=o.y; xv[4*k+2]=o.z; xv[4*k+3]=o.w;
            if (l < NL - 1) *(float4*)(xr + e) = o;
            ss2 += o.x*o.x + o.y*o.y + o.z*o.z + o.w*o.w;
        }
        ss2 = warp_sum(ss2);
        float r2 = rsqrtf(ss2 * (1.f/1024.f) + EPS);
        if (lane == 0) s_ir[t] = r2;

        if (l == NL - 1){
            // final: store normalized fp16 token directly (x * r2 * fw)
            half* xo = g_xh + (size_t)(tok0 + t) * D_MODEL;
#pragma unroll
            for (int k = 0; k < 8; k++){
                int e = k * 128 + lane * 4;
                float4 f = *(const float4*)(fw + e);
                half2 ha = __floats2half2_rn(xv[4*k+0]*r2*f.x, xv[4*k+1]*r2*f.y);
                half2 hb = __floats2half2_rn(xv[4*k+2]*r2*f.z, xv[4*k+3]*r2*f.w);
                uint2 pk; pk.x = *(uint32_t*)&ha; pk.y = *(uint32_t*)&hb;
                *(uint2*)(xo + e) = pk;
            }
        }
        __syncthreads();

        if (l < NL - 1){
            int off2 = (l + 1) * D_MODEL + c;
            float a2  = sigmoidf_(lam[off2]);
            float vn2 = vv[off2] * n1w[off2];
            float h2 = 0.f;
#pragma unroll
            for (int tt = 0; tt < TC; tt++)
                h2 = fmaf(a2, h2, (vn2 * s_ir[tt]) * sx[tt * D_MODEL + c]);
            g_hfin[l + 1][blockIdx.x * D_MODEL + c] = h2;
            __syncthreads();
            if (c == 0){ __threadfence(); atomicAdd(&g_flag[l + 1][blockIdx.x], 1u); }
        }
    }
}

// =========================================================================
// logits: TPB tokens per block, all 8 warps do stage-1 then stage-2.
// A-fragments via __ldg (L1-resident tables); high occupancy (5 blocks/SM).
// =========================================================================
__global__ __launch_bounds__(256, 5) void k_logits(float* __restrict__ out){
    __shared__ half s_x [32  * PITCH];
    __shared__ half s_Yt[160 * PITCH];

    int tid = threadIdx.x;
    int w = tid >> 5, lane = tid & 31, g = lane >> 2, tg = lane & 3;
    int tokBase = blockIdx.x * TPB;

    const uint4* c2f = (const uint4*)g_c2h;
    const uint4* c1f = (const uint4*)g_c1h;

    // this warp's stage-2 tile range (contiguous, mt-major)
    int start = (w * 260) >> 3;
    int end   = ((w + 1) * 260) >> 3;

    for (int i = 0; i < TPB; i++){
        // load token (already normalized fp16)
        {
            int e = tid * 4;
            uint2 pk = *(const uint2*)(g_xh + (size_t)(tokBase + i) * D_MODEL + e);
            *(uint2*)(s_x + (e >> 5) * PITCH + (e & 31)) = pk;
        }
        __syncthreads();

        // ---- stage 1: 40 tiles over 8 warps (5 each) ----
        for (int id = w * 5; id < w * 5 + 5; id++){
            int mt = id >> 2, nt = id & 3;
            uint4 qb0 = __ldg(&c2f[(mt * 32 + lane) * 2 + 0]);
            uint4 qb1 = __ldg(&c2f[(mt * 32 + lane) * 2 + 1]);
            float a0c = 0.f, a1c = 0.f, a2c = 0.f, a3c = 0.f;
            int ac = 2 * tg;
            const half* xb = s_x + (nt*8 + g) * PITCH;
            uint32_t B0 = *(const uint32_t*)(xb + ac);
            uint32_t B1 = *(const uint32_t*)(xb + ac + 8);
            mma16816(a0c, a1c, a2c, a3c, qb0.x, qb0.y, qb0.z, qb0.w, B0, B1);
            B0 = *(const uint32_t*)(xb + ac + 16);
            B1 = *(const uint32_t*)(xb + ac + 24);
            mma16816(a0c, a1c, a2c, a3c, qb1.x, qb1.y, qb1.z, qb1.w, B0, B1);
            int col = nt * 8 + 2 * tg;
            *(half2*)(s_Yt + (mt*16 + g    ) * PITCH + col) = __floats2half2_rn(a0c, a1c);
            *(half2*)(s_Yt + (mt*16 + g + 8) * PITCH + col) = __floats2half2_rn(a2c, a3c);
        }
        __syncthreads();

        // ---- stage 2: 260 tiles over 8 warps; A-frags reload on mt change ----
        float* op = out + (size_t)(tokBase + i) * (V1N * V2N);
        int curMt = start / 20;
        uint4 qa0 = __ldg(&c1f[(curMt * 32 + lane) * 2 + 0]);
        uint4 qa1 = __ldg(&c1f[(curMt * 32 + lane) * 2 + 1]);
        for (int id = start; id < end; id++){
            int mt = id / 20, nt = id - mt * 20;
            if (mt != curMt){
                curMt = mt;
                qa0 = __ldg(&c1f[(mt * 32 + lane) * 2 + 0]);
                qa1 = __ldg(&c1f[(mt * 32 + lane) * 2 + 1]);
            }
            float a0c = 0.f, a1c = 0.f, a2c = 0.f, a3c = 0.f;
            int ac = 2 * tg;
            const half* yb = s_Yt + (nt*8 + g) * PITCH;
            uint32_t B0 = *(const uint32_t*)(yb + ac);
            uint32_t B1 = *(const uint32_t*)(yb + ac + 8);
            mma16816(a0c, a1c, a2c, a3c, qa0.x, qa0.y, qa0.z, qa0.w, B0, B1);
            B0 = *(const uint32_t*)(yb + ac + 16);
            B1 = *(const uint32_t*)(yb + ac + 24);
            mma16816(a0c, a1c, a2c, a3c, qa1.x, qa1.y, qa1.z, qa1.w, B0, B1);
            int r0 = mt * 16 + g, col = nt * 8 + 2 * tg;
            __stcs((float2*)(op + r0 * V2N + col), make_float2(a0c, a1c));
            if (r0 + 8 < V1N)
                __stcs((float2*)(op + (r0 + 8) * V2N + col), make_float2(a2c, a3c));
        }
        __syncthreads();
    }
}

// ---------------- launch --------------------------------------------------
extern "C" void kernel_launch(void* const* d_in, const int* in_sizes, int n_in,
                              void* d_out, int out_size){
    const int*   ids = (const int*)  d_in[0];
    const float* c1  = (const float*)d_in[1];
    const float* c2  = (const float*)d_in[2];
    const float* lam = (const float*)d_in[3];
    const float* u   = (const float*)d_in[4];
    const float* v   = (const float*)d_in[5];
    const float* w1  = (const float*)d_in[6];
    const float* w2  = (const float*)d_in[7];
    const float* n1w = (const float*)d_in[8];
    const float* n2w = (const float*)d_in[9];
    const float* fw  = (const float*)d_in[10];
    float* out = (float*)d_out;

    const int smem = TC * D_MODEL * sizeof(float);   // 128 KB dynamic
    static bool attr_set = false;
    if (!attr_set){
        cudaFuncSetAttribute(k_model, cudaFuncAttributeMaxDynamicSharedMemorySize, smem);
        attr_set = true;
    }

    k_model<<<NBLK, 1024, smem>>>(ids, c1, c2, lam, u, v, w1, w2, n1w, n2w, fw);
    k_logits<<<NTOK / TPB, 256>>>(out);
}

// round 10
// speedup vs baseline: 1.1872x; 1.0548x over previous
#include <cuda_runtime.h>
#include <cuda_fp16.h>
#include <cstdint>

#define D_MODEL 1024
#define BB 2
#define SS 2048
#define NTOK (BB*SS)
#define V1N 200
#define V2N 160
#define NL 8
#define TC 32
#define NC (SS/TC)     /* 64 */
#define NBLK (BB*NC)   /* 128 */
#define EPS 1e-6f
#define PITCH 40
#define TPB 4
#define SCW 36          /* scratch row stride (floats): <=2-way on 64b STS */

// ---------------- scratch -------------------------------------------------
__device__ half  g_xh[NTOK * D_MODEL];         // final normalized token (fp16)
__device__ float g_hfin[NL][NBLK * D_MODEL];   // per-layer chunk-local scan results
__device__ unsigned g_flag[NL][NBLK];          // monotone per-block ready flags
__device__ uint32_t g_c1h[13 * 256];           // c1 fp16 frags: [mt][lane][ks][j]
__device__ uint32_t g_c2h[10 * 256];           // c2 fp16 frags: [mt][lane][ks][j]

// ---------------- helpers -------------------------------------------------
__device__ __forceinline__ float warp_sum(float v){
#pragma unroll
    for (int o = 16; o; o >>= 1) v += __shfl_xor_sync(0xffffffffu, v, o);
    return v;
}
__device__ __forceinline__ float sigmoidf_(float x){ return 1.f / (1.f + expf(-x)); }
__device__ __forceinline__ float geluf_(float x){
    float x3 = x * x * x;
    return 0.5f * x * (1.f + tanhf(0.7978845608028654f * (x + 0.044715f * x3)));
}
__device__ __forceinline__ unsigned ld_acq(const unsigned* p){
    unsigned v;
    asm volatile("ld.acquire.gpu.global.u32 %0, [%1];" : "=r"(v) : "l"(p));
    return v;
}
__device__ __forceinline__ void mma16816(float& d0, float& d1, float& d2, float& d3,
                                         uint32_t a0, uint32_t a1, uint32_t a2, uint32_t a3,
                                         uint32_t b0, uint32_t b1){
    asm volatile(
        "mma.sync.aligned.m16n8k16.row.col.f32.f16.f16.f32 "
        "{%0,%1,%2,%3},{%4,%5,%6,%7},{%8,%9},{%0,%1,%2,%3};\n"
        : "+f"(d0), "+f"(d1), "+f"(d2), "+f"(d3)
        : "r"(a0), "r"(a1), "r"(a2), "r"(a3), "r"(b0), "r"(b1));
}

// =========================================================================
// model kernel: embed + 8 fused layers; x stays in smem; wavefront flags.
// =========================================================================
__global__ __launch_bounds__(1024, 1) void k_model(
    const int* __restrict__ ids, const float* __restrict__ c1,
    const float* __restrict__ c2, const float* __restrict__ lam,
    const float* __restrict__ uu, const float* __restrict__ vv,
    const float* __restrict__ w1, const float* __restrict__ w2,
    const float* __restrict__ n1w, const float* __restrict__ n2w,
    const float* __restrict__ fw)
{
    extern __shared__ float sx[];              // TC * D_MODEL = 128 KB
    __shared__ float s_n2w[D_MODEL], s_w1x[D_MODEL], s_w1y[D_MODEL];
    __shared__ float s_w2a[D_MODEL], s_w2b[D_MODEL];
    __shared__ float s_ir[TC];
    __shared__ unsigned s_base;

    int b  = blockIdx.x >> 6;
    int ch = blockIdx.x & (NC - 1);
    int c  = threadIdx.x;
    int t  = c >> 5, lane = c & 31;
    int tok0 = b * SS + ch * TC;

    if (c == 0) s_base = g_flag[0][blockIdx.x];   // epoch baseline (replay-safe)

    // ---- embed (warp = token) into smem ----
    {
        int id = ids[tok0 + t];
        const float* r1 = c1 + (id / V2N) * 32;
        const float* r2 = c2 + (id % V2N) * 32;
        float* xr = sx + t * D_MODEL;
        float ss = 0.f;
#pragma unroll
        for (int k = 0; k < 8; k++){
            int e = k * 128 + lane * 4;
            float a = r1[e >> 5];
            float4 bq = *(const float4*)(r2 + (e & 31));
            float4 v4; v4.x = a*bq.x; v4.y = a*bq.y; v4.z = a*bq.z; v4.w = a*bq.w;
            *(float4*)(xr + e) = v4;
            ss += v4.x*v4.x + v4.y*v4.y + v4.z*v4.z + v4.w*v4.w;
        }
        ss = warp_sum(ss);
        if (lane == 0) s_ir[t] = rsqrtf(ss * (1.f/1024.f) + EPS);
    }
    __syncthreads();

    // ---- phase A for layer 0; publish flag[0] ----
    {
        float a0  = sigmoidf_(lam[c]);
        float vn0 = vv[c] * n1w[c];
        float h = 0.f;
#pragma unroll
        for (int tt = 0; tt < TC; tt++)
            h = fmaf(a0, h, (vn0 * s_ir[tt]) * sx[tt * D_MODEL + c]);
        g_hfin[0][blockIdx.x * D_MODEL + c] = h;
    }
    __syncthreads();
    if (c == 0){ __threadfence(); atomicAdd(&g_flag[0][blockIdx.x], 1u); }

    // ---- block 0: pack c1/c2 into fp16 MMA A-fragment tables ----
    if (blockIdx.x == 0){
        const int T1 = 13 * 256, T2 = 10 * 256;
        for (int idx = c; idx < T1 + T2; idx += 1024){
            bool is1 = idx < T1;
            int rem  = is1 ? idx : idx - T1;
            int j = rem & 3, ks = (rem >> 2) & 1, ln = (rem >> 3) & 31, mt = rem >> 8;
            int gg = ln >> 2, tg2 = ln & 3;
            int row = mt * 16 + gg + (j & 1) * 8;
            int col = ks * 16 + 2 * tg2 + ((j >> 1) & 1) * 8;
            if (is1){
                uint32_t val = 0;
                if (row < V1N){
                    half2 h = __floats2half2_rn(c1[row * 32 + col], c1[row * 32 + col + 1]);
                    val = *(uint32_t*)&h;
                }
                g_c1h[rem] = val;
            } else {
                half2 h = __floats2half2_rn(c2[row * 32 + col], c2[row * 32 + col + 1]);
                g_c2h[rem] = *(uint32_t*)&h;
            }
        }
    }

    // =================== 8 fused layers ===================
    for (int l = 0; l < NL; l++){
        unsigned tgt = s_base + 1;
        if (c < ch){
            const unsigned* fp = &g_flag[l][b * NC + c];
            while (ld_acq(fp) < tgt) {}
        }
        __syncthreads();

        float w_n2 = n2w[l * D_MODEL + c];
        float2 w1p = ((const float2*)(w1 + (size_t)l * D_MODEL * 2))[c];
        float w2av = w2[(size_t)l * 2 * D_MODEL + c];
        float w2bv = w2[(size_t)l * 2 * D_MODEL + D_MODEL + c];

        int off = l * D_MODEL + c;
        float a  = sigmoidf_(lam[off]);
        float vn = vv[off] * n1w[off];
        float un = uu[off];
        float aT = a * a; aT *= aT; aT *= aT; aT *= aT; aT *= aT;   // a^32

        const float* hf = g_hfin[l] + (size_t)b * NC * D_MODEL + c;
        float carry = 0.f;
#pragma unroll 16
        for (int k = 0; k < ch; k++)
            carry = fmaf(aT, carry, __ldcg(hf + (size_t)k * D_MODEL));

        s_n2w[c] = w_n2; s_w1x[c] = w1p.x; s_w1y[c] = w1p.y;
        s_w2a[c] = w2av; s_w2b[c] = w2bv;

        float h = carry;
#pragma unroll
        for (int tt = 0; tt < TC; tt++){
            float xv = sx[tt * D_MODEL + c];
            h = fmaf(a, h, (vn * s_ir[tt]) * xv);
            sx[tt * D_MODEL + c] = fmaf(un, h, xv);
        }
        __syncthreads();

        float* xr = sx + t * D_MODEL;
        float xv[32];
        float ss = 0.f;
#pragma unroll
        for (int k = 0; k < 8; k++){
            float4 q = *(const float4*)(xr + k * 128 + lane * 4);
            xv[4*k]=q.x; xv[4*k+1]=q.y; xv[4*k+2]=q.z; xv[4*k+3]=q.w;
            ss += q.x*q.x + q.y*q.y + q.z*q.z + q.w*q.w;
        }
        ss = warp_sum(ss);
        float invr = rsqrtf(ss * (1.f/1024.f) + EPS);

        float d0 = 0.f, d1 = 0.f;
#pragma unroll
        for (int k = 0; k < 8; k++){
            int e = k * 128 + lane * 4;
            float4 nw = *(const float4*)(s_n2w + e);
            float4 wx = *(const float4*)(s_w1x + e);
            float4 wy = *(const float4*)(s_w1y + e);
#pragma unroll
            for (int r = 0; r < 4; r++){
                float hh = xv[4*k+r] * invr * ((const float*)&nw)[r];
                d0 = fmaf(hh, ((const float*)&wx)[r], d0);
                d1 = fmaf(hh, ((const float*)&wy)[r], d1);
            }
        }
        d0 = warp_sum(d0);
        d1 = warp_sum(d1);
        float g0 = geluf_(d0), g1 = geluf_(d1);

        float ss2 = 0.f;
#pragma unroll
        for (int k = 0; k < 8; k++){
            int e = k * 128 + lane * 4;
            float4 wa = *(const float4*)(s_w2a + e);
            float4 wb = *(const float4*)(s_w2b + e);
            float4 o;
            o.x = xv[4*k+0] + g0*wa.x + g1*wb.x;
            o.y = xv[4*k+1] + g0*wa.y + g1*wb.y;
            o.z = xv[4*k+2] + g0*wa.z + g1*wb.z;
            o.w = xv[4*k+3] + g0*wa.w + g1*wb.w;
            xv[4*k+0]=o.x; xv[4*k+1]=o.y; xv[4*k+2]=o.z; xv[4*k+3]=o.w;
            if (l < NL - 1) *(float4*)(xr + e) = o;
            ss2 += o.x*o.x + o.y*o.y + o.z*o.z + o.w*o.w;
        }
        ss2 = warp_sum(ss2);
        float r2 = rsqrtf(ss2 * (1.f/1024.f) + EPS);
        if (lane == 0) s_ir[t] = r2;

        if (l == NL - 1){
            half* xo = g_xh + (size_t)(tok0 + t) * D_MODEL;
#pragma unroll
            for (int k = 0; k < 8; k++){
                int e = k * 128 + lane * 4;
                float4 f = *(const float4*)(fw + e);
                half2 ha = __floats2half2_rn(xv[4*k+0]*r2*f.x, xv[4*k+1]*r2*f.y);
                half2 hb = __floats2half2_rn(xv[4*k+2]*r2*f.z, xv[4*k+3]*r2*f.w);
                uint2 pk; pk.x = *(uint32_t*)&ha; pk.y = *(uint32_t*)&hb;
                *(uint2*)(xo + e) = pk;
            }
        }
        __syncthreads();

        if (l < NL - 1){
            int off2 = (l + 1) * D_MODEL + c;
            float a2  = sigmoidf_(lam[off2]);
            float vn2 = vv[off2] * n1w[off2];
            float h2 = 0.f;
#pragma unroll
            for (int tt = 0; tt < TC; tt++)
                h2 = fmaf(a2, h2, (vn2 * s_ir[tt]) * sx[tt * D_MODEL + c]);
            g_hfin[l + 1][blockIdx.x * D_MODEL + c] = h2;
            __syncthreads();
            if (c == 0){ __threadfence(); atomicAdd(&g_flag[l + 1][blockIdx.x], 1u); }
        }
    }
}

// =========================================================================
// logits: TPB tokens/block. Stage-2 works in quads of 4 nt-tiles; output
// staged through per-warp smem scratch -> fully coalesced 128B STG.
// =========================================================================
__global__ __launch_bounds__(256, 4) void k_logits(float* __restrict__ out){
    __shared__ half  s_x [32  * PITCH];
    __shared__ half  s_Yt[160 * PITCH];
    __shared__ float s_scr[8 * 16 * SCW];      // per-warp 16x32 staging (padded)

    int tid = threadIdx.x;
    int w = tid >> 5, lane = tid & 31, g = lane >> 2, tg = lane & 3;
    int tokBase = blockIdx.x * TPB;

    const uint4* c2f = (const uint4*)g_c2h;
    const uint4* c1f = (const uint4*)g_c1h;
    float* sc = s_scr + w * 16 * SCW;

    // this warp's stage-2 quad range (65 quads = 13 mt x 5 ntq, mt-major)
    int qstart = (w * 65) >> 3;
    int qend   = ((w + 1) * 65) >> 3;

    for (int i = 0; i < TPB; i++){
        // load token (already normalized fp16)
        {
            int e = tid * 4;
            uint2 pk = *(const uint2*)(g_xh + (size_t)(tokBase + i) * D_MODEL + e);
            *(uint2*)(s_x + (e >> 5) * PITCH + (e & 31)) = pk;
        }
        __syncthreads();

        // ---- stage 1: 40 tiles over 8 warps (5 each) ----
        for (int id = w * 5; id < w * 5 + 5; id++){
            int mt = id >> 2, nt = id & 3;
            uint4 qb0 = __ldg(&c2f[(mt * 32 + lane) * 2 + 0]);
            uint4 qb1 = __ldg(&c2f[(mt * 32 + lane) * 2 + 1]);
            float a0c = 0.f, a1c = 0.f, a2c = 0.f, a3c = 0.f;
            int ac = 2 * tg;
            const half* xb = s_x + (nt*8 + g) * PITCH;
            uint32_t B0 = *(const uint32_t*)(xb + ac);
            uint32_t B1 = *(const uint32_t*)(xb + ac + 8);
            mma16816(a0c, a1c, a2c, a3c, qb0.x, qb0.y, qb0.z, qb0.w, B0, B1);
            B0 = *(const uint32_t*)(xb + ac + 16);
            B1 = *(const uint32_t*)(xb + ac + 24);
            mma16816(a0c, a1c, a2c, a3c, qb1.x, qb1.y, qb1.z, qb1.w, B0, B1);
            int col = nt * 8 + 2 * tg;
            *(half2*)(s_Yt + (mt*16 + g    ) * PITCH + col) = __floats2half2_rn(a0c, a1c);
            *(half2*)(s_Yt + (mt*16 + g + 8) * PITCH + col) = __floats2half2_rn(a2c, a3c);
        }
        __syncthreads();

        // ---- stage 2: quads of 4 nt tiles; smem-staged coalesced stores ----
        float* op = out + (size_t)(tokBase + i) * (V1N * V2N);
        int curMt = -1;
        uint4 qa0, qa1;
        for (int q = qstart; q < qend; q++){
            int mt = q / 5, ntq = q - mt * 5;
            if (mt != curMt){
                curMt = mt;
                qa0 = __ldg(&c1f[(mt * 32 + lane) * 2 + 0]);
                qa1 = __ldg(&c1f[(mt * 32 + lane) * 2 + 1]);
            }
            float acc[4][4];
#pragma unroll
            for (int n4 = 0; n4 < 4; n4++){
                int nt = ntq * 4 + n4;
                acc[n4][0] = acc[n4][1] = acc[n4][2] = acc[n4][3] = 0.f;
                int ac = 2 * tg;
                const half* yb = s_Yt + (nt*8 + g) * PITCH;
                uint32_t B0 = *(const uint32_t*)(yb + ac);
                uint32_t B1 = *(const uint32_t*)(yb + ac + 8);
                mma16816(acc[n4][0], acc[n4][1], acc[n4][2], acc[n4][3],
                         qa0.x, qa0.y, qa0.z, qa0.w, B0, B1);
                B0 = *(const uint32_t*)(yb + ac + 16);
                B1 = *(const uint32_t*)(yb + ac + 24);
                mma16816(acc[n4][0], acc[n4][1], acc[n4][2], acc[n4][3],
                         qa1.x, qa1.y, qa1.z, qa1.w, B0, B1);
            }
            // stage to smem (rows g and g+8)
#pragma unroll
            for (int n4 = 0; n4 < 4; n4++){
                int col = n4 * 8 + 2 * tg;
                *(float2*)(sc + g * SCW + col)       = make_float2(acc[n4][0], acc[n4][1]);
                *(float2*)(sc + (g + 8) * SCW + col) = make_float2(acc[n4][2], acc[n4][3]);
            }
            __syncwarp();
            // coalesced stores: 4 warp-wide STG.128, 4 full lines each
            float* opb = op + (mt * 16) * V2N + ntq * 32;
#pragma unroll
            for (int j = 0; j < 4; j++){
                int row = j * 4 + (lane >> 3);
                int col = (lane & 7) * 4;
                if (mt * 16 + row < V1N){
                    float4 vq = *(const float4*)(sc + row * SCW + col);
                    __stcs((float4*)(opb + row * V2N + col), vq);
                }
            }
            __syncwarp();
        }
        __syncthreads();
    }
}

// ---------------- launch --------------------------------------------------
extern "C" void kernel_launch(void* const* d_in, const int* in_sizes, int n_in,
                              void* d_out, int out_size){
    const int*   ids = (const int*)  d_in[0];
    const float* c1  = (const float*)d_in[1];
    const float* c2  = (const float*)d_in[2];
    const float* lam = (const float*)d_in[3];
    const float* u   = (const float*)d_in[4];
    const float* v   = (const float*)d_in[5];
    const float* w1  = (const float*)d_in[6];
    const float* w2  = (const float*)d_in[7];
    const float* n1w = (const float*)d_in[8];
    const float* n2w = (const float*)d_in[9];
    const float* fw  = (const float*)d_in[10];
    float* out = (float*)d_out;

    const int smem = TC * D_MODEL * sizeof(float);   // 128 KB dynamic
    static bool attr_set = false;
    if (!attr_set){
        cudaFuncSetAttribute(k_model, cudaFuncAttributeMaxDynamicSharedMemorySize, smem);
        attr_set = true;
    }

    k_model<<<NBLK, 1024, smem>>>(ids, c1, c2, lam, u, v, w1, w2, n1w, n2w, fw);
    k_logits<<<NTOK / TPB, 256>>>(out);
}

// round 13
// speedup vs baseline: 1.3287x; 1.1193x over previous
#include <cuda_runtime.h>
#include <cuda_fp16.h>
#include <cstdint>

#define D_MODEL 1024
#define BB 2
#define SS 2048
#define NTOK (BB*SS)
#define V1N 200
#define V2N 160
#define NL 8
#define TC 32
#define NC (SS/TC)     /* 64 */
#define NBLK (BB*NC)   /* 128 */
#define EPS 1e-6f
#define PITCH 40
#define TPB 4

// ---------------- scratch -------------------------------------------------
__device__ half  g_xh[NTOK * D_MODEL];         // final normalized token (fp16)
__device__ float g_hfin[NL][NBLK * D_MODEL];   // per-layer chunk-local scan results
__device__ unsigned g_flag[NL][NBLK];          // monotone per-block ready flags
__device__ uint32_t g_c1h[13 * 256];           // c1 fp16 frags: [mt][lane][ks][j]
__device__ uint32_t g_c2h[10 * 256];           // c2 fp16 frags: [mt][lane][ks][j]

// ---------------- helpers -------------------------------------------------
__device__ __forceinline__ float warp_sum(float v){
#pragma unroll
    for (int o = 16; o; o >>= 1) v += __shfl_xor_sync(0xffffffffu, v, o);
    return v;
}
__device__ __forceinline__ float sigmoidf_(float x){ return 1.f / (1.f + expf(-x)); }
__device__ __forceinline__ float geluf_(float x){
    float x3 = x * x * x;
    return 0.5f * x * (1.f + tanhf(0.7978845608028654f * (x + 0.044715f * x3)));
}
__device__ __forceinline__ unsigned ld_acq(const unsigned* p){
    unsigned v;
    asm volatile("ld.acquire.gpu.global.u32 %0, [%1];" : "=r"(v) : "l"(p));
    return v;
}
__device__ __forceinline__ void mma16816(float& d0, float& d1, float& d2, float& d3,
                                         uint32_t a0, uint32_t a1, uint32_t a2, uint32_t a3,
                                         uint32_t b0, uint32_t b1){
    asm volatile(
        "mma.sync.aligned.m16n8k16.row.col.f32.f16.f16.f32 "
        "{%0,%1,%2,%3},{%4,%5,%6,%7},{%8,%9},{%0,%1,%2,%3};\n"
        : "+f"(d0), "+f"(d1), "+f"(d2), "+f"(d3)
        : "r"(a0), "r"(a1), "r"(a2), "r"(a3), "r"(b0), "r"(b1));
}

// =========================================================================
// model kernel: embed + 8 fused layers; x stays in smem; wavefront flags.
// =========================================================================
__global__ __launch_bounds__(1024, 1) void k_model(
    const int* __restrict__ ids, const float* __restrict__ c1,
    const float* __restrict__ c2, const float* __restrict__ lam,
    const float* __restrict__ uu, const float* __restrict__ vv,
    const float* __restrict__ w1, const float* __restrict__ w2,
    const float* __restrict__ n1w, const float* __restrict__ n2w,
    const float* __restrict__ fw)
{
    extern __shared__ float sx[];              // TC * D_MODEL = 128 KB
    __shared__ float s_n2w[D_MODEL], s_w1x[D_MODEL], s_w1y[D_MODEL];
    __shared__ float s_w2a[D_MODEL], s_w2b[D_MODEL];
    __shared__ float s_ir[TC];
    __shared__ unsigned s_base;

    int b  = blockIdx.x >> 6;
    int ch = blockIdx.x & (NC - 1);
    int c  = threadIdx.x;
    int t  = c >> 5, lane = c & 31;
    int tok0 = b * SS + ch * TC;

    if (c == 0) s_base = g_flag[0][blockIdx.x];   // epoch baseline (replay-safe)

    // ---- embed (warp = token) into smem ----
    {
        int id = ids[tok0 + t];
        const float* r1 = c1 + (id / V2N) * 32;
        const float* r2 = c2 + (id % V2N) * 32;
        float* xr = sx + t * D_MODEL;
        float ss = 0.f;
#pragma unroll
        for (int k = 0; k < 8; k++){
            int e = k * 128 + lane * 4;
            float a = r1[e >> 5];
            float4 bq = *(const float4*)(r2 + (e & 31));
            float4 v4; v4.x = a*bq.x; v4.y = a*bq.y; v4.z = a*bq.z; v4.w = a*bq.w;
            *(float4*)(xr + e) = v4;
            ss += v4.x*v4.x + v4.y*v4.y + v4.z*v4.z + v4.w*v4.w;
        }
        ss = warp_sum(ss);
        if (lane == 0) s_ir[t] = rsqrtf(ss * (1.f/1024.f) + EPS);
    }
    __syncthreads();

    // ---- phase A for layer 0; publish flag[0] ----
    {
        float a0  = sigmoidf_(lam[c]);
        float vn0 = vv[c] * n1w[c];
        float h = 0.f;
#pragma unroll
        for (int tt = 0; tt < TC; tt++)
            h = fmaf(a0, h, (vn0 * s_ir[tt]) * sx[tt * D_MODEL + c]);
        g_hfin[0][blockIdx.x * D_MODEL + c] = h;
    }
    __syncthreads();
    if (c == 0){ __threadfence(); atomicAdd(&g_flag[0][blockIdx.x], 1u); }

    // ---- block 0: pack c1/c2 into fp16 MMA A-fragment tables ----
    if (blockIdx.x == 0){
        const int T1 = 13 * 256, T2 = 10 * 256;
        for (int idx = c; idx < T1 + T2; idx += 1024){
            bool is1 = idx < T1;
            int rem  = is1 ? idx : idx - T1;
            int j = rem & 3, ks = (rem >> 2) & 1, ln = (rem >> 3) & 31, mt = rem >> 8;
            int gg = ln >> 2, tg2 = ln & 3;
            int row = mt * 16 + gg + (j & 1) * 8;
            int col = ks * 16 + 2 * tg2 + ((j >> 1) & 1) * 8;
            if (is1){
                uint32_t val = 0;
                if (row < V1N){
                    half2 h = __floats2half2_rn(c1[row * 32 + col], c1[row * 32 + col + 1]);
                    val = *(uint32_t*)&h;
                }
                g_c1h[rem] = val;
            } else {
                half2 h = __floats2half2_rn(c2[row * 32 + col], c2[row * 32 + col + 1]);
                g_c2h[rem] = *(uint32_t*)&h;
            }
        }
    }

    // =================== 8 fused layers ===================
    for (int l = 0; l < NL; l++){
        unsigned tgt = s_base + 1;
        if (c < ch){
            const unsigned* fp = &g_flag[l][b * NC + c];
            while (ld_acq(fp) < tgt) {}
        }
        __syncthreads();

        float w_n2 = n2w[l * D_MODEL + c];
        float2 w1p = ((const float2*)(w1 + (size_t)l * D_MODEL * 2))[c];
        float w2av = w2[(size_t)l * 2 * D_MODEL + c];
        float w2bv = w2[(size_t)l * 2 * D_MODEL + D_MODEL + c];

        int off = l * D_MODEL + c;
        float a  = sigmoidf_(lam[off]);
        float vn = vv[off] * n1w[off];
        float un = uu[off];
        float aT = a * a; aT *= aT; aT *= aT; aT *= aT; aT *= aT;   // a^32

        const float* hf = g_hfin[l] + (size_t)b * NC * D_MODEL + c;
        float carry = 0.f;
#pragma unroll 16
        for (int k = 0; k < ch; k++)
            carry = fmaf(aT, carry, __ldcg(hf + (size_t)k * D_MODEL));

        s_n2w[c] = w_n2; s_w1x[c] = w1p.x; s_w1y[c] = w1p.y;
        s_w2a[c] = w2av; s_w2b[c] = w2bv;

        float h = carry;
#pragma unroll
        for (int tt = 0; tt < TC; tt++){
            float xv = sx[tt * D_MODEL + c];
            h = fmaf(a, h, (vn * s_ir[tt]) * xv);
            sx[tt * D_MODEL + c] = fmaf(un, h, xv);
        }
        __syncthreads();

        float* xr = sx + t * D_MODEL;
        float xv[32];
        float ss = 0.f;
#pragma unroll
        for (int k = 0; k < 8; k++){
            float4 q = *(const float4*)(xr + k * 128 + lane * 4);
            xv[4*k]=q.x; xv[4*k+1]=q.y; xv[4*k+2]=q.z; xv[4*k+3]=q.w;
            ss += q.x*q.x + q.y*q.y + q.z*q.z + q.w*q.w;
        }
        ss = warp_sum(ss);
        float invr = rsqrtf(ss * (1.f/1024.f) + EPS);

        float d0 = 0.f, d1 = 0.f;
#pragma unroll
        for (int k = 0; k < 8; k++){
            int e = k * 128 + lane * 4;
            float4 nw = *(const float4*)(s_n2w + e);
            float4 wx = *(const float4*)(s_w1x + e);
            float4 wy = *(const float4*)(s_w1y + e);
#pragma unroll
            for (int r = 0; r < 4; r++){
                float hh = xv[4*k+r] * invr * ((const float*)&nw)[r];
                d0 = fmaf(hh, ((const float*)&wx)[r], d0);
                d1 = fmaf(hh, ((const float*)&wy)[r], d1);
            }
        }
        d0 = warp_sum(d0);
        d1 = warp_sum(d1);
        float g0 = geluf_(d0), g1 = geluf_(d1);

        float ss2 = 0.f;
#pragma unroll
        for (int k = 0; k < 8; k++){
            int e = k * 128 + lane * 4;
            float4 wa = *(const float4*)(s_w2a + e);
            float4 wb = *(const float4*)(s_w2b + e);
            float4 o;
            o.x = xv[4*k+0] + g0*wa.x + g1*wb.x;
            o.y = xv[4*k+1] + g0*wa.y + g1*wb.y;
            o.z = xv[4*k+2] + g0*wa.z + g1*wb.z;
            o.w = xv[4*k+3] + g0*wa.w + g1*wb.w;
            xv[4*k+0]=o.x; xv[4*k+1]=o.y; xv[4*k+2]=o.z; xv[4*k+3]=o.w;
            if (l < NL - 1) *(float4*)(xr + e) = o;
            ss2 += o.x*o.x + o.y*o.y + o.z*o.z + o.w*o.w;
        }
        ss2 = warp_sum(ss2);
        float r2 = rsqrtf(ss2 * (1.f/1024.f) + EPS);
        if (lane == 0) s_ir[t] = r2;

        if (l == NL - 1){
            half* xo = g_xh + (size_t)(tok0 + t) * D_MODEL;
#pragma unroll
            for (int k = 0; k < 8; k++){
                int e = k * 128 + lane * 4;
                float4 f = *(const float4*)(fw + e);
                half2 ha = __floats2half2_rn(xv[4*k+0]*r2*f.x, xv[4*k+1]*r2*f.y);
                half2 hb = __floats2half2_rn(xv[4*k+2]*r2*f.z, xv[4*k+3]*r2*f.w);
                uint2 pk; pk.x = *(uint32_t*)&ha; pk.y = *(uint32_t*)&hb;
                *(uint2*)(xo + e) = pk;
            }
        }
        __syncthreads();

        if (l < NL - 1){
            int off2 = (l + 1) * D_MODEL + c;
            float a2  = sigmoidf_(lam[off2]);
            float vn2 = vv[off2] * n1w[off2];
            float h2 = 0.f;
#pragma unroll
            for (int tt = 0; tt < TC; tt++)
                h2 = fmaf(a2, h2, (vn2 * s_ir[tt]) * sx[tt * D_MODEL + c]);
            g_hfin[l + 1][blockIdx.x * D_MODEL + c] = h2;
            __syncthreads();
            if (c == 0){ __threadfence(); atomicAdd(&g_flag[l + 1][blockIdx.x], 1u); }
        }
    }
}

// =========================================================================
// logits: TPB tokens/block. Stage-2 quads staged through XOR-swizzled fp16
// scratch: conflict-free STS/LDS + full-line STG.128 (48 wf / 2KB output).
// =========================================================================
__global__ __launch_bounds__(256, 4) void k_logits(float* __restrict__ out){
    __shared__ half s_x [32  * PITCH];
    __shared__ half s_Yt[160 * PITCH];
    __shared__ half s_scr[8 * 16 * 64];        // per warp: 16 rows x 128B, swizzled

    int tid = threadIdx.x;
    int w = tid >> 5, lane = tid & 31, g = lane >> 2, tg = lane & 3;
    int tokBase = blockIdx.x * TPB;

    const uint4* c2f = (const uint4*)g_c2h;
    const uint4* c1f = (const uint4*)g_c1h;
    half* scH = s_scr + w * 16 * 64;

    // this warp's stage-2 quad range (65 quads = 13 mt x 5 ntq, mt-major)
    int qstart = (w * 65) >> 3;
    int qend   = ((w + 1) * 65) >> 3;
    int u = lane & 7;                           // 8B unit within a row

    for (int i = 0; i < TPB; i++){
        // load token (already normalized fp16)
        {
            int e = tid * 4;
            uint2 pk = *(const uint2*)(g_xh + (size_t)(tokBase + i) * D_MODEL + e);
            *(uint2*)(s_x + (e >> 5) * PITCH + (e & 31)) = pk;
        }
        __syncthreads();

        // ---- stage 1: 40 tiles over 8 warps (5 each) ----
        for (int id = w * 5; id < w * 5 + 5; id++){
            int mt = id >> 2, nt = id & 3;
            uint4 qb0 = __ldg(&c2f[(mt * 32 + lane) * 2 + 0]);
            uint4 qb1 = __ldg(&c2f[(mt * 32 + lane) * 2 + 1]);
            float a0c = 0.f, a1c = 0.f, a2c = 0.f, a3c = 0.f;
            int ac = 2 * tg;
            const half* xb = s_x + (nt*8 + g) * PITCH;
            uint32_t B0 = *(const uint32_t*)(xb + ac);
            uint32_t B1 = *(const uint32_t*)(xb + ac + 8);
            mma16816(a0c, a1c, a2c, a3c, qb0.x, qb0.y, qb0.z, qb0.w, B0, B1);
            B0 = *(const uint32_t*)(xb + ac + 16);
            B1 = *(const uint32_t*)(xb + ac + 24);
            mma16816(a0c, a1c, a2c, a3c, qb1.x, qb1.y, qb1.z, qb1.w, B0, B1);
            int col = nt * 8 + 2 * tg;
            *(half2*)(s_Yt + (mt*16 + g    ) * PITCH + col) = __floats2half2_rn(a0c, a1c);
            *(half2*)(s_Yt + (mt*16 + g + 8) * PITCH + col) = __floats2half2_rn(a2c, a3c);
        }
        __syncthreads();

        // ---- stage 2: quads of 4 nt tiles; fp16 swizzled staging ----
        float* op = out + (size_t)(tokBase + i) * (V1N * V2N);
        int curMt = -1;
        uint4 qa0, qa1;
        for (int q = qstart; q < qend; q++){
            int mt = q / 5, ntq = q - mt * 5;
            if (mt != curMt){
                curMt = mt;
                qa0 = __ldg(&c1f[(mt * 32 + lane) * 2 + 0]);
                qa1 = __ldg(&c1f[(mt * 32 + lane) * 2 + 1]);
            }
            float acc[4][4];
#pragma unroll
            for (int n4 = 0; n4 < 4; n4++){
                int nt = ntq * 4 + n4;
                acc[n4][0] = acc[n4][1] = acc[n4][2] = acc[n4][3] = 0.f;
                int ac = 2 * tg;
                const half* yb = s_Yt + (nt*8 + g) * PITCH;
                uint32_t B0 = *(const uint32_t*)(yb + ac);
                uint32_t B1 = *(const uint32_t*)(yb + ac + 8);
                mma16816(acc[n4][0], acc[n4][1], acc[n4][2], acc[n4][3],
                         qa0.x, qa0.y, qa0.z, qa0.w, B0, B1);
                B0 = *(const uint32_t*)(yb + ac + 16);
                B1 = *(const uint32_t*)(yb + ac + 24);
                mma16816(acc[n4][0], acc[n4][1], acc[n4][2], acc[n4][3],
                         qa1.x, qa1.y, qa1.z, qa1.w, B0, B1);
            }
            // stage fp16, chunk' = n4 ^ (row&7): banks (n4^g)*4+tg, conflict-free
#pragma unroll
            for (int n4 = 0; n4 < 4; n4++){
                int chB = (n4 ^ g) * 8;        // chunk offset in halfs
                half2 h0 = __floats2half2_rn(acc[n4][0], acc[n4][1]);
                half2 h1 = __floats2half2_rn(acc[n4][2], acc[n4][3]);
                *(half2*)(scH + (g    ) * 64 + chB + tg * 2) = h0;
                *(half2*)(scH + (g + 8) * 64 + chB + tg * 2) = h1;
            }
            __syncwarp();
            // readback LDS.64 (one row per quarter-warp phase) + full-line STG
#pragma unroll
            for (int j = 0; j < 4; j++){
                int r = (lane >> 3) + 4 * j;
                int chp = ((u >> 1) ^ (r & 7)) * 8;
                uint2 pk = *(const uint2*)(scH + r * 64 + chp + (u & 1) * 4);
                half2* hp = (half2*)&pk;
                float2 f0 = __half22float2(hp[0]);
                float2 f1 = __half22float2(hp[1]);
                int orow = mt * 16 + r;
                if (orow < V1N)
                    __stcs((float4*)(op + orow * V2N + ntq * 32 + u * 4),
                           make_float4(f0.x, f0.y, f1.x, f1.y));
            }
            __syncwarp();
        }
        __syncthreads();
    }
}

// ---------------- launch --------------------------------------------------
extern "C" void kernel_launch(void* const* d_in, const int* in_sizes, int n_in,
                              void* d_out, int out_size){
    const int*   ids = (const int*)  d_in[0];
    const float* c1  = (const float*)d_in[1];
    const float* c2  = (const float*)d_in[2];
    const float* lam = (const float*)d_in[3];
    const float* u   = (const float*)d_in[4];
    const float* v   = (const float*)d_in[5];
    const float* w1  = (const float*)d_in[6];
    const float* w2  = (const float*)d_in[7];
    const float* n1w = (const float*)d_in[8];
    const float* n2w = (const float*)d_in[9];
    const float* fw  = (const float*)d_in[10];
    float* out = (float*)d_out;

    const int smem = TC * D_MODEL * sizeof(float);   // 128 KB dynamic
    static bool attr_set = false;
    if (!attr_set){
        cudaFuncSetAttribute(k_model, cudaFuncAttributeMaxDynamicSharedMemorySize, smem);
        attr_set = true;
    }

    k_model<<<NBLK, 1024, smem>>>(ids, c1, c2, lam, u, v, w1, w2, n1w, n2w, fw);
    k_logits<<<NTOK / TPB, 256>>>(out);
}